// round 1
// baseline (speedup 1.0000x reference)
#include <cuda_runtime.h>
#include <cuda_bf16.h>

// Focal BCE-with-logits, mean-reduced.
//   p = sigmoid(x)
//   loss = target==1 ? -ALPHA*(1-p)^G * ln(p) : -(1-ALPHA)*p^G * ln(1-p)
// Reformulated to 3 MUFU ops/element:
//   t = 2^(-x*log2e) = exp(-x); l = log2(1+t)
//   log2(p) = -l ; log2(1-p) = -x*log2e - l = d
//   pos: loss = (ALPHA*ln2*l)       * 2^(G*d)
//   neg: loss = (-(1-ALPHA)*ln2*d)  * 2^(G*(-l))

#define GRID_BLOCKS 1184
#define BLOCK_THREADS 256

__device__ float g_partials[GRID_BLOCKS];

__device__ __forceinline__ float fast_ex2(float x) {
    float r; asm("ex2.approx.ftz.f32 %0, %1;" : "=f"(r) : "f"(x)); return r;
}
__device__ __forceinline__ float fast_lg2(float x) {
    float r; asm("lg2.approx.ftz.f32 %0, %1;" : "=f"(r) : "f"(x)); return r;
}

__device__ __forceinline__ float focal_elem(float x, int tg) {
    const float LOG2E = 1.4426950408889634f;
    const float LN2   = 0.6931471805599453f;
    const float GAMMA = 0.2f;
    const float C1 =  0.6f * LN2;   //  alpha * ln2
    const float C0 = -0.4f * LN2;   // -(1-alpha) * ln2
    float nxl = -x * LOG2E;              // log2(exp(-x))
    float t   = fast_ex2(nxl);           // exp(-x)            (MUFU 1)
    float l   = fast_lg2(1.0f + t);      // log2(1+exp(-x))    (MUFU 2)
    float d   = nxl - l;                 // log2(1-p)
    bool  pos = (tg == 1);
    float log2b = pos ? d : -l;          // log2 of the modulating prob
    float w     = pos ? (C1 * l) : (C0 * d);   // coef * (-ln a), >= 0
    float powb  = fast_ex2(GAMMA * log2b);     //                 (MUFU 3)
    return powb * w;
}

__device__ __forceinline__ float block_reduce(float acc) {
    __shared__ float sw[BLOCK_THREADS / 32];
    int lane = threadIdx.x & 31;
    int wid  = threadIdx.x >> 5;
    #pragma unroll
    for (int off = 16; off > 0; off >>= 1)
        acc += __shfl_down_sync(0xffffffffu, acc, off);
    if (lane == 0) sw[wid] = acc;
    __syncthreads();
    float v = 0.0f;
    if (wid == 0) {
        v = (lane < (BLOCK_THREADS / 32)) ? sw[lane] : 0.0f;
        #pragma unroll
        for (int off = (BLOCK_THREADS / 64); off > 0; off >>= 1)
            v += __shfl_down_sync(0xffffffffu, v, off);
    }
    return v;  // valid in thread 0 only
}

__global__ void focal_main(const float* __restrict__ logits,
                           const int*   __restrict__ target,
                           long long n) {
    const long long n4     = n >> 2;
    const long long stride = (long long)gridDim.x * blockDim.x;
    const long long tid0   = (long long)blockIdx.x * blockDim.x + threadIdx.x;
    const float4* lg4 = reinterpret_cast<const float4*>(logits);
    const int4*   tg4 = reinterpret_cast<const int4*>(target);

    float acc = 0.0f;
    for (long long i = tid0; i < n4; i += stride) {
        float4 x = __ldcs(lg4 + i);
        int4   t = __ldcs(tg4 + i);
        acc += focal_elem(x.x, t.x);
        acc += focal_elem(x.y, t.y);
        acc += focal_elem(x.z, t.z);
        acc += focal_elem(x.w, t.w);
    }
    // scalar tail (n not multiple of 4)
    for (long long i = (n4 << 2) + tid0; i < n; i += stride)
        acc += focal_elem(__ldcs(logits + i), __ldcs(target + i));

    float v = block_reduce(acc);
    if (threadIdx.x == 0) g_partials[blockIdx.x] = v;
}

__global__ void focal_reduce(float* __restrict__ out, float inv_n) {
    float acc = 0.0f;
    for (int i = threadIdx.x; i < GRID_BLOCKS; i += blockDim.x)
        acc += g_partials[i];
    float v = block_reduce(acc);
    if (threadIdx.x == 0) out[0] = v * inv_n;
}

extern "C" void kernel_launch(void* const* d_in, const int* in_sizes, int n_in,
                              void* d_out, int out_size) {
    const float* logits = (const float*)d_in[0];
    const int*   target = (const int*)d_in[1];
    long long n = (long long)in_sizes[0];
    focal_main<<<GRID_BLOCKS, BLOCK_THREADS>>>(logits, target, n);
    focal_reduce<<<1, BLOCK_THREADS>>>((float*)d_out, 1.0f / (float)n);
}

// round 3
// speedup vs baseline: 1.1092x; 1.1092x over previous
#include <cuda_runtime.h>
#include <cuda_bf16.h>

// Focal BCE-with-logits, mean-reduced. Single fused kernel.
//   p = sigmoid(x)
//   loss = target==1 ? -ALPHA*(1-p)^G * ln(p) : -(1-ALPHA)*p^G * ln(1-p)
// 3 MUFU ops/element:
//   nxl = -x*log2e ; t = 2^nxl = exp(-x) ; l = log2(1+t)
//   log2(p) = -l ; log2(1-p) = nxl - l = d
//   pos: loss = (ALPHA*ln2*l)      * 2^(G*d)
//   neg: loss = (-(1-ALPHA)*ln2*d) * 2^(G*(-l))

#define GRID_BLOCKS 1184
#define BLOCK_THREADS 256

__device__ float        g_partials[GRID_BLOCKS];
__device__ unsigned int g_ticket;   // zero-init at load; last block resets to 0 each launch

__device__ __forceinline__ float fast_ex2(float x) {
    float r; asm("ex2.approx.ftz.f32 %0, %1;" : "=f"(r) : "f"(x)); return r;
}
__device__ __forceinline__ float fast_lg2(float x) {
    float r; asm("lg2.approx.ftz.f32 %0, %1;" : "=f"(r) : "f"(x)); return r;
}

__device__ __forceinline__ float focal_elem(float x, int tg) {
    const float LOG2E = 1.4426950408889634f;
    const float LN2   = 0.6931471805599453f;
    const float GAMMA = 0.2f;
    const float C1 =  0.6f * LN2;   //  alpha * ln2
    const float C0 = -0.4f * LN2;   // -(1-alpha) * ln2
    float nxl = -x * LOG2E;
    float t   = fast_ex2(nxl);           // exp(-x)
    float l   = fast_lg2(1.0f + t);      // log2(1+exp(-x))
    float d   = nxl - l;                 // log2(1-p)
    bool  pos = (tg == 1);
    float log2b = pos ? d : -l;
    float w     = pos ? (C1 * l) : (C0 * d);
    return fast_ex2(GAMMA * log2b) * w;
}

__device__ __forceinline__ float block_reduce(float acc) {
    __shared__ float sw[BLOCK_THREADS / 32];
    int lane = threadIdx.x & 31;
    int wid  = threadIdx.x >> 5;
    #pragma unroll
    for (int off = 16; off > 0; off >>= 1)
        acc += __shfl_down_sync(0xffffffffu, acc, off);
    if (lane == 0) sw[wid] = acc;
    __syncthreads();
    float v = 0.0f;
    if (wid == 0) {
        v = (lane < (BLOCK_THREADS / 32)) ? sw[lane] : 0.0f;
        #pragma unroll
        for (int off = (BLOCK_THREADS / 64); off > 0; off >>= 1)
            v += __shfl_down_sync(0xffffffffu, v, off);
    }
    return v;  // valid in thread 0 only
}

__global__ void __launch_bounds__(BLOCK_THREADS)
focal_fused(const float* __restrict__ logits,
            const int*   __restrict__ target,
            float* __restrict__ out,
            long long n, float inv_n) {
    const long long n8     = n >> 3;                        // 8 elems / thread / iter
    const long long stride = (long long)gridDim.x * blockDim.x;
    const long long tid0   = (long long)blockIdx.x * blockDim.x + threadIdx.x;
    const float4* lg4 = reinterpret_cast<const float4*>(logits);
    const int4*   tg4 = reinterpret_cast<const int4*>(target);

    float acc = 0.0f;
    for (long long i = tid0; i < n8; i += stride) {
        // 4 independent 16B loads front-batched (MLP_p1 = 4)
        float4 x0 = __ldcs(lg4 + 2 * i);
        float4 x1 = __ldcs(lg4 + 2 * i + 1);
        int4   t0 = __ldcs(tg4 + 2 * i);
        int4   t1 = __ldcs(tg4 + 2 * i + 1);
        acc += focal_elem(x0.x, t0.x);
        acc += focal_elem(x0.y, t0.y);
        acc += focal_elem(x0.z, t0.z);
        acc += focal_elem(x0.w, t0.w);
        acc += focal_elem(x1.x, t1.x);
        acc += focal_elem(x1.y, t1.y);
        acc += focal_elem(x1.z, t1.z);
        acc += focal_elem(x1.w, t1.w);
    }
    // scalar tail (n not multiple of 8)
    for (long long i = (n8 << 3) + tid0; i < n; i += stride)
        acc += focal_elem(__ldcs(logits + i), __ldcs(target + i));

    float v = block_reduce(acc);

    // ---- last-block final reduction (deterministic; no second kernel) ----
    __shared__ bool is_last;
    if (threadIdx.x == 0) {
        g_partials[blockIdx.x] = v;
        __threadfence();
        unsigned int t = atomicAdd(&g_ticket, 1u);
        is_last = (t == (unsigned int)(gridDim.x - 1));
    }
    __syncthreads();
    if (is_last) {
        float a = 0.0f;
        for (int i = threadIdx.x; i < (int)gridDim.x; i += blockDim.x)
            a += g_partials[i];
        float s = block_reduce(a);
        if (threadIdx.x == 0) {
            out[0]   = s * inv_n;
            g_ticket = 0;          // reset for next launch / graph replay
        }
    }
}

extern "C" void kernel_launch(void* const* d_in, const int* in_sizes, int n_in,
                              void* d_out, int out_size) {
    const float* logits = (const float*)d_in[0];
    const int*   target = (const int*)d_in[1];
    long long n = (long long)in_sizes[0];
    focal_fused<<<GRID_BLOCKS, BLOCK_THREADS>>>(logits, target, (float*)d_out,
                                                n, 1.0f / (float)n);
}